// round 3
// baseline (speedup 1.0000x reference)
#include <cuda_runtime.h>
#include <math.h>

#define BSZ   8192
#define IND   1024
#define OUTD  1024
#define BK    16
#define BM    128
#define BN    128
#define PAD   132          // BM + 4 to de-conflict smem
#define NSPLIT 8
#define NCHUNK 64          // column-reduction row chunks

// ---- scratch (static device globals; no dynamic allocation) ----
__device__ float g_u [(size_t)BSZ * OUTD];          // 32 MB
__device__ float g_yn[(size_t)BSZ * OUTD];          // 32 MB
__device__ float g_P [NCHUNK * OUTD];               // partial column sums
__device__ float g_m [OUTD];
__device__ float g_rate[OUTD];
__device__ float g_S [(size_t)NSPLIT * OUTD * IND]; // 32 MB split-K partials

// ============================================================
// GEMM1: u[m,n] = sum_k x[m,k] * W[n,k] + b[n]
// Both operands row-major with K contiguous -> transpose on smem store.
// ============================================================
__global__ __launch_bounds__(256, 2) void gemm1_kernel(
    const float* __restrict__ X, const float* __restrict__ W,
    const float* __restrict__ bias)
{
    __shared__ float As[BK][PAD];
    __shared__ float Bs[BK][PAD];
    const int t  = threadIdx.x;
    const int m0 = blockIdx.y * BM;
    const int n0 = blockIdx.x * BN;
    const int tx = t & 15, ty = t >> 4;

    float acc[8][8];
#pragma unroll
    for (int i = 0; i < 8; i++)
#pragma unroll
        for (int j = 0; j < 8; j++) acc[i][j] = 0.f;

    const int row0 = t >> 2;   // 0..63
    const int kc   = t & 3;    // which float4 of the 16-wide k slab

    for (int k0 = 0; k0 < IND; k0 += BK) {
#pragma unroll
        for (int r = 0; r < 2; ++r) {
            const int row = row0 + r * 64;
            float4 va = *reinterpret_cast<const float4*>(
                &X[(size_t)(m0 + row) * IND + k0 + kc * 4]);
            As[kc*4+0][row] = va.x; As[kc*4+1][row] = va.y;
            As[kc*4+2][row] = va.z; As[kc*4+3][row] = va.w;
            float4 vb = *reinterpret_cast<const float4*>(
                &W[(size_t)(n0 + row) * IND + k0 + kc * 4]);
            Bs[kc*4+0][row] = vb.x; Bs[kc*4+1][row] = vb.y;
            Bs[kc*4+2][row] = vb.z; Bs[kc*4+3][row] = vb.w;
        }
        __syncthreads();
#pragma unroll
        for (int kk = 0; kk < BK; ++kk) {
            float a[8], b[8];
            float4 a0 = *reinterpret_cast<const float4*>(&As[kk][ty*8]);
            float4 a1 = *reinterpret_cast<const float4*>(&As[kk][ty*8+4]);
            float4 b0 = *reinterpret_cast<const float4*>(&Bs[kk][tx*8]);
            float4 b1 = *reinterpret_cast<const float4*>(&Bs[kk][tx*8+4]);
            a[0]=a0.x; a[1]=a0.y; a[2]=a0.z; a[3]=a0.w;
            a[4]=a1.x; a[5]=a1.y; a[6]=a1.z; a[7]=a1.w;
            b[0]=b0.x; b[1]=b0.y; b[2]=b0.z; b[3]=b0.w;
            b[4]=b1.x; b[5]=b1.y; b[6]=b1.z; b[7]=b1.w;
#pragma unroll
            for (int i = 0; i < 8; i++)
#pragma unroll
                for (int j = 0; j < 8; j++)
                    acc[i][j] = fmaf(a[i], b[j], acc[i][j]);
        }
        __syncthreads();
    }

    float4 bb0 = *reinterpret_cast<const float4*>(&bias[n0 + tx*8]);
    float4 bb1 = *reinterpret_cast<const float4*>(&bias[n0 + tx*8 + 4]);
#pragma unroll
    for (int i = 0; i < 8; i++) {
        float* dst = &g_u[(size_t)(m0 + ty*8 + i) * OUTD + n0 + tx*8];
        float4 o0 = make_float4(acc[i][0]+bb0.x, acc[i][1]+bb0.y,
                                acc[i][2]+bb0.z, acc[i][3]+bb0.w);
        float4 o1 = make_float4(acc[i][4]+bb1.x, acc[i][5]+bb1.y,
                                acc[i][6]+bb1.z, acc[i][7]+bb1.w);
        *reinterpret_cast<float4*>(dst)     = o0;
        *reinterpret_cast<float4*>(dst + 4) = o1;
    }
}

// ============================================================
// Per-row softmax + negate-non-maximal: yn[b,:] from u[b,:]
// ============================================================
__global__ __launch_bounds__(256) void softmax_neg_kernel()
{
    const int b = blockIdx.x;
    const int t = threadIdx.x;
    const unsigned full = 0xffffffffu;

    float4 v = reinterpret_cast<const float4*>(&g_u[(size_t)b * OUTD])[t];

    // thread-local argmax (first occurrence)
    float mx = v.x; int ai = t*4;
    if (v.y > mx) { mx = v.y; ai = t*4+1; }
    if (v.z > mx) { mx = v.z; ai = t*4+2; }
    if (v.w > mx) { mx = v.w; ai = t*4+3; }

#pragma unroll
    for (int off = 16; off > 0; off >>= 1) {
        float omx = __shfl_down_sync(full, mx, off);
        int   oai = __shfl_down_sync(full, ai, off);
        if (omx > mx || (omx == mx && oai < ai)) { mx = omx; ai = oai; }
    }
    __shared__ float smx[8];
    __shared__ int   sai[8];
    __shared__ float ssum[8];
    const int warp = t >> 5, lane = t & 31;
    if (lane == 0) { smx[warp] = mx; sai[warp] = ai; }
    __syncthreads();
    if (t == 0) {
        for (int w = 1; w < 8; ++w)
            if (smx[w] > smx[0] || (smx[w] == smx[0] && sai[w] < sai[0])) {
                smx[0] = smx[w]; sai[0] = sai[w];
            }
    }
    __syncthreads();
    const float MX = smx[0];
    const int   AI = sai[0];

    float4 e;
    e.x = expf(v.x - MX); e.y = expf(v.y - MX);
    e.z = expf(v.z - MX); e.w = expf(v.w - MX);
    float s = e.x + e.y + e.z + e.w;
#pragma unroll
    for (int off = 16; off > 0; off >>= 1) s += __shfl_down_sync(full, s, off);
    if (lane == 0) ssum[warp] = s;
    __syncthreads();
    if (t == 0) {
        float tot = 0.f;
        for (int w = 0; w < 8; ++w) tot += ssum[w];
        ssum[0] = tot;
    }
    __syncthreads();
    const float inv = 1.f / ssum[0];

    float4 o;
    o.x = (t*4+0 == AI) ? e.x*inv : -e.x*inv;
    o.y = (t*4+1 == AI) ? e.y*inv : -e.y*inv;
    o.z = (t*4+2 == AI) ? e.z*inv : -e.z*inv;
    o.w = (t*4+3 == AI) ? e.w*inv : -e.w*inv;
    reinterpret_cast<float4*>(&g_yn[(size_t)b * OUTD])[t] = o;
}

// ============================================================
// Adaptive rate: rate[o] = 1e-3 * |1 - ||W[o,:]||_2|^0.5
// ============================================================
__global__ __launch_bounds__(256) void rate_kernel(const float* __restrict__ W)
{
    const int o = blockIdx.x;
    const int t = threadIdx.x;
    const unsigned full = 0xffffffffu;
    float4 w = reinterpret_cast<const float4*>(&W[(size_t)o * IND])[t];
    float s = w.x*w.x + w.y*w.y + w.z*w.z + w.w*w.w;
#pragma unroll
    for (int off = 16; off > 0; off >>= 1) s += __shfl_down_sync(full, s, off);
    __shared__ float ssum[8];
    const int warp = t >> 5, lane = t & 31;
    if (lane == 0) ssum[warp] = s;
    __syncthreads();
    if (t == 0) {
        float tot = 0.f;
        for (int w2 = 0; w2 < 8; ++w2) tot += ssum[w2];
        float norm = sqrtf(tot);
        g_rate[o] = 1e-3f * sqrtf(fabsf(1.f - norm));
    }
}

// ============================================================
// Column reduction: m[o] = mean_b(yn[b,o] * u[b,o]); two stages (no atomics)
// ============================================================
__global__ __launch_bounds__(256) void col_partial_kernel()
{
    const int o = blockIdx.x * 256 + threadIdx.x;
    const int c = blockIdx.y;
    const int r0 = c * (BSZ / NCHUNK);
    float acc = 0.f;
#pragma unroll 4
    for (int r = 0; r < BSZ / NCHUNK; ++r) {
        const size_t off = (size_t)(r0 + r) * OUTD + o;
        acc += g_yn[off] * g_u[off];
    }
    g_P[c * OUTD + o] = acc;
}

__global__ __launch_bounds__(256) void m_final_kernel()
{
    const int o = blockIdx.x * 256 + threadIdx.x;
    float acc = 0.f;
#pragma unroll
    for (int c = 0; c < NCHUNK; ++c) acc += g_P[c * OUTD + o];
    g_m[o] = acc * (1.f / (float)BSZ);
}

// ============================================================
// GEMM2 (split-K): S[s][o,i] = sum_{k in chunk s} yn[k,o] * x[k,i]
// Both operands naturally [k][m]-layout: direct float4 smem stores.
// ============================================================
__global__ __launch_bounds__(256, 2) void gemm2_kernel(const float* __restrict__ X)
{
    __shared__ float As[BK][PAD];
    __shared__ float Bs[BK][PAD];
    const int t  = threadIdx.x;
    const int i0 = blockIdx.x * BN;               // IN
    const int o0 = blockIdx.y * BM;               // OUT
    const int kbase = blockIdx.z * (BSZ / NSPLIT);
    const int tx = t & 15, ty = t >> 4;

    float acc[8][8];
#pragma unroll
    for (int i = 0; i < 8; i++)
#pragma unroll
        for (int j = 0; j < 8; j++) acc[i][j] = 0.f;

    const int kr0 = t >> 5;        // 0..7
    const int col = (t & 31) * 4;  // 0..124

    for (int k0 = 0; k0 < BSZ / NSPLIT; k0 += BK) {
#pragma unroll
        for (int r = 0; r < 2; ++r) {
            const int kr = kr0 + r * 8;
            float4 va = *reinterpret_cast<const float4*>(
                &g_yn[(size_t)(kbase + k0 + kr) * OUTD + o0 + col]);
            *reinterpret_cast<float4*>(&As[kr][col]) = va;
            float4 vb = *reinterpret_cast<const float4*>(
                &X[(size_t)(kbase + k0 + kr) * IND + i0 + col]);
            *reinterpret_cast<float4*>(&Bs[kr][col]) = vb;
        }
        __syncthreads();
#pragma unroll
        for (int kk = 0; kk < BK; ++kk) {
            float a[8], b[8];
            float4 a0 = *reinterpret_cast<const float4*>(&As[kk][ty*8]);
            float4 a1 = *reinterpret_cast<const float4*>(&As[kk][ty*8+4]);
            float4 b0 = *reinterpret_cast<const float4*>(&Bs[kk][tx*8]);
            float4 b1 = *reinterpret_cast<const float4*>(&Bs[kk][tx*8+4]);
            a[0]=a0.x; a[1]=a0.y; a[2]=a0.z; a[3]=a0.w;
            a[4]=a1.x; a[5]=a1.y; a[6]=a1.z; a[7]=a1.w;
            b[0]=b0.x; b[1]=b0.y; b[2]=b0.z; b[3]=b0.w;
            b[4]=b1.x; b[5]=b1.y; b[6]=b1.z; b[7]=b1.w;
#pragma unroll
            for (int i = 0; i < 8; i++)
#pragma unroll
                for (int j = 0; j < 8; j++)
                    acc[i][j] = fmaf(a[i], b[j], acc[i][j]);
        }
        __syncthreads();
    }

    float* dstbase = &g_S[(size_t)blockIdx.z * OUTD * IND];
#pragma unroll
    for (int i = 0; i < 8; i++) {
        float* dst = dstbase + (size_t)(o0 + ty*8 + i) * IND + i0 + tx*8;
        *reinterpret_cast<float4*>(dst) =
            make_float4(acc[i][0], acc[i][1], acc[i][2], acc[i][3]);
        *reinterpret_cast<float4*>(dst + 4) =
            make_float4(acc[i][4], acc[i][5], acc[i][6], acc[i][7]);
    }
}

// ============================================================
// Epilogue: out[o,i] = rate[o] * (sum_s S[s][o,i]/B - m[o]*W[o,i])
// One block per output row o.
// ============================================================
__global__ __launch_bounds__(256) void epilogue_kernel(
    const float* __restrict__ W, float* __restrict__ out)
{
    const int o = blockIdx.x;
    const int t = threadIdx.x;
    const float m = g_m[o];
    const float r = g_rate[o];
    float4 wv = reinterpret_cast<const float4*>(&W[(size_t)o * IND])[t];
    float4 s = make_float4(0.f, 0.f, 0.f, 0.f);
#pragma unroll
    for (int sp = 0; sp < NSPLIT; ++sp) {
        float4 p = reinterpret_cast<const float4*>(
            &g_S[(size_t)sp * OUTD * IND + (size_t)o * IND])[t];
        s.x += p.x; s.y += p.y; s.z += p.z; s.w += p.w;
    }
    const float invB = 1.f / (float)BSZ;
    float4 ov;
    ov.x = r * (s.x * invB - m * wv.x);
    ov.y = r * (s.y * invB - m * wv.y);
    ov.z = r * (s.z * invB - m * wv.z);
    ov.w = r * (s.w * invB - m * wv.w);
    reinterpret_cast<float4*>(&out[(size_t)o * IND])[t] = ov;
}

// ============================================================
extern "C" void kernel_launch(void* const* d_in, const int* in_sizes, int n_in,
                              void* d_out, int out_size)
{
    const float* x = (const float*)d_in[0];   // [8192, 1024]
    const float* W = (const float*)d_in[1];   // [1024, 1024]
    const float* b = (const float*)d_in[2];   // [1024]
    float* out = (float*)d_out;               // [1024, 1024]

    gemm1_kernel<<<dim3(OUTD / BN, BSZ / BM), 256>>>(x, W, b);
    softmax_neg_kernel<<<BSZ, 256>>>();
    rate_kernel<<<OUTD, 256>>>(W);
    col_partial_kernel<<<dim3(OUTD / 256, NCHUNK), 256>>>();
    m_final_kernel<<<OUTD / 256, 256>>>();
    gemm2_kernel<<<dim3(IND / BN, OUTD / BM, NSPLIT), 256>>>(x);
    epilogue_kernel<<<OUTD, 256>>>(W, out);
}

// round 5
// speedup vs baseline: 1.2766x; 1.2766x over previous
#include <cuda_runtime.h>
#include <cstdint>
#include <math.h>

#define BSZ   8192
#define IND   1024
#define OUTD  1024
#define NSPLIT 8
#define NCHUNK 512

// ---- scratch (static device globals; no dynamic allocation) ----
__device__ float g_u  [(size_t)BSZ * OUTD];          // 32 MB
__device__ float g_yn [(size_t)BSZ * OUTD];          // 32 MB
__device__ float g_xT [(size_t)IND * BSZ];           // 32 MB  x^T  [i][b]
__device__ float g_ynT[(size_t)OUTD * BSZ];          // 32 MB  yn^T [o][b]
__device__ float g_P  [NCHUNK * OUTD];               // partial column sums
__device__ float g_m  [OUTD];
__device__ float g_rate[OUTD];
__device__ float g_S  [(size_t)NSPLIT * OUTD * IND]; // 32 MB split-K partials

__device__ __forceinline__ float tf32_round(float x) {
    float y;
    asm("cvt.rna.tf32.f32 %0, %1;" : "=f"(y) : "f"(x));
    return y;
}

__device__ __forceinline__ void mma_m16n8k8(float c[4], const uint32_t a[4],
                                            const uint32_t b[2])
{
    asm volatile(
        "mma.sync.aligned.m16n8k8.row.col.f32.tf32.tf32.f32 "
        "{%0,%1,%2,%3}, {%4,%5,%6,%7}, {%8,%9}, {%0,%1,%2,%3};\n"
        : "+f"(c[0]), "+f"(c[1]), "+f"(c[2]), "+f"(c[3])
        : "r"(a[0]), "r"(a[1]), "r"(a[2]), "r"(a[3]),
          "r"(b[0]), "r"(b[1]));
}

#define SMEM_STRIDE 36
#define TILE_FLOATS (128 * SMEM_STRIDE)
#define SMEM_BYTES  (4 * TILE_FLOATS * 4)   // Ahi, Alo, Bhi, Blo = 73728 B

// ============================================================
// tf32x3 mma.sync GEMM: D[m0+r][n0+c] = sum_k A[m][k]*B[n][k] (+bias[n])
// A: [Mtot][lda] K-major, B: [Ntot][ldb] K-major. K-chunk = 1024 per z.
// CTA 128x128, 8 warps (2M x 4N), warp tile 64x32, stage K = 32.
// ============================================================
__global__ __launch_bounds__(256, 2) void gemm_tf32x3_kernel(
    const float* __restrict__ A, int lda,
    const float* __restrict__ B, int ldb,
    int kzstep, float* __restrict__ dstBase, int ldd, size_t zstride,
    const float* __restrict__ bias)
{
    extern __shared__ float smem[];
    float* sAhi = smem;
    float* sAlo = smem + TILE_FLOATS;
    float* sBhi = smem + 2 * TILE_FLOATS;
    float* sBlo = smem + 3 * TILE_FLOATS;

    const int t     = threadIdx.x;
    const int lane  = t & 31;
    const int warp  = t >> 5;
    const int warpM = warp & 1;   // 0..1
    const int warpN = warp >> 1;  // 0..3
    const int m0    = blockIdx.y * 128;
    const int n0    = blockIdx.x * 128;
    const int kbase = blockIdx.z * kzstep;
    float* dst = dstBase + (size_t)blockIdx.z * zstride;

    const int gr = lane >> 2;     // 0..7
    const int kc = lane & 3;      // 0..3

    float c[4][4][4];
#pragma unroll
    for (int mt = 0; mt < 4; ++mt)
#pragma unroll
        for (int nt = 0; nt < 4; ++nt)
#pragma unroll
            for (int e = 0; e < 4; ++e) c[mt][nt][e] = 0.f;

    const int frow0 = t >> 3;          // fill row base (0..31), +32 per j
    const int fk4   = (t & 7) * 4;     // fill k offset

    for (int s = 0; s < 32; ++s) {
        const int ks0 = kbase + s * 32;
        __syncthreads();
#pragma unroll
        for (int j = 0; j < 4; ++j) {
            const int row = frow0 + 32 * j;
            const int so  = row * SMEM_STRIDE + fk4;

            float4 va = *reinterpret_cast<const float4*>(
                &A[(size_t)(m0 + row) * lda + ks0 + fk4]);
            float4 ah, al;
            ah.x = tf32_round(va.x); al.x = tf32_round(va.x - ah.x);
            ah.y = tf32_round(va.y); al.y = tf32_round(va.y - ah.y);
            ah.z = tf32_round(va.z); al.z = tf32_round(va.z - ah.z);
            ah.w = tf32_round(va.w); al.w = tf32_round(va.w - ah.w);
            *reinterpret_cast<float4*>(&sAhi[so]) = ah;
            *reinterpret_cast<float4*>(&sAlo[so]) = al;

            float4 vb = *reinterpret_cast<const float4*>(
                &B[(size_t)(n0 + row) * ldb + ks0 + fk4]);
            float4 bh, bl;
            bh.x = tf32_round(vb.x); bl.x = tf32_round(vb.x - bh.x);
            bh.y = tf32_round(vb.y); bl.y = tf32_round(vb.y - bh.y);
            bh.z = tf32_round(vb.z); bl.z = tf32_round(vb.z - bh.z);
            bh.w = tf32_round(vb.w); bl.w = tf32_round(vb.w - bh.w);
            *reinterpret_cast<float4*>(&sBhi[so]) = bh;
            *reinterpret_cast<float4*>(&sBlo[so]) = bl;
        }
        __syncthreads();

        const uint32_t* pAh = reinterpret_cast<const uint32_t*>(sAhi);
        const uint32_t* pAl = reinterpret_cast<const uint32_t*>(sAlo);
        const uint32_t* pBh = reinterpret_cast<const uint32_t*>(sBhi);
        const uint32_t* pBl = reinterpret_cast<const uint32_t*>(sBlo);

#pragma unroll
        for (int ks = 0; ks < 4; ++ks) {
            const int k0 = ks * 8 + kc;
            uint32_t ah[4][4], bh[4][2];

#pragma unroll
            for (int mt = 0; mt < 4; ++mt) {
                const int r = warpM * 64 + mt * 16 + gr;
                ah[mt][0] = pAh[r * SMEM_STRIDE + k0];
                ah[mt][1] = pAh[(r + 8) * SMEM_STRIDE + k0];
                ah[mt][2] = pAh[r * SMEM_STRIDE + k0 + 4];
                ah[mt][3] = pAh[(r + 8) * SMEM_STRIDE + k0 + 4];
            }
#pragma unroll
            for (int nt = 0; nt < 4; ++nt) {
                const int n = warpN * 32 + nt * 8 + gr;
                bh[nt][0] = pBh[n * SMEM_STRIDE + k0];
                bh[nt][1] = pBh[n * SMEM_STRIDE + k0 + 4];
            }
            // hi * hi
#pragma unroll
            for (int mt = 0; mt < 4; ++mt)
#pragma unroll
                for (int nt = 0; nt < 4; ++nt)
                    mma_m16n8k8(c[mt][nt], ah[mt], bh[nt]);

            // hi * lo
            {
                uint32_t bl[4][2];
#pragma unroll
                for (int nt = 0; nt < 4; ++nt) {
                    const int n = warpN * 32 + nt * 8 + gr;
                    bl[nt][0] = pBl[n * SMEM_STRIDE + k0];
                    bl[nt][1] = pBl[n * SMEM_STRIDE + k0 + 4];
                }
#pragma unroll
                for (int mt = 0; mt < 4; ++mt)
#pragma unroll
                    for (int nt = 0; nt < 4; ++nt)
                        mma_m16n8k8(c[mt][nt], ah[mt], bl[nt]);
            }
            // lo * hi
            {
                uint32_t al[4][4];
#pragma unroll
                for (int mt = 0; mt < 4; ++mt) {
                    const int r = warpM * 64 + mt * 16 + gr;
                    al[mt][0] = pAl[r * SMEM_STRIDE + k0];
                    al[mt][1] = pAl[(r + 8) * SMEM_STRIDE + k0];
                    al[mt][2] = pAl[r * SMEM_STRIDE + k0 + 4];
                    al[mt][3] = pAl[(r + 8) * SMEM_STRIDE + k0 + 4];
                }
#pragma unroll
                for (int mt = 0; mt < 4; ++mt)
#pragma unroll
                    for (int nt = 0; nt < 4; ++nt)
                        mma_m16n8k8(c[mt][nt], al[mt], bh[nt]);
            }
        }
    }

    // ---- epilogue: C regs -> global (float2 per half-tile) ----
#pragma unroll
    for (int mt = 0; mt < 4; ++mt) {
        const int r = m0 + warpM * 64 + mt * 16 + gr;
#pragma unroll
        for (int nt = 0; nt < 4; ++nt) {
            const int cc = n0 + warpN * 32 + nt * 8 + (lane & 3) * 2;
            float2 v0 = make_float2(c[mt][nt][0], c[mt][nt][1]);
            float2 v1 = make_float2(c[mt][nt][2], c[mt][nt][3]);
            if (bias) {
                const float b0 = __ldg(&bias[cc]);
                const float b1 = __ldg(&bias[cc + 1]);
                v0.x += b0; v0.y += b1;
                v1.x += b0; v1.y += b1;
            }
            *reinterpret_cast<float2*>(&dst[(size_t)r * ldd + cc])       = v0;
            *reinterpret_cast<float2*>(&dst[(size_t)(r + 8) * ldd + cc]) = v1;
        }
    }
}

// ============================================================
// Per-row softmax + negate-non-maximal: yn[b,:] from u[b,:]
// ============================================================
__global__ __launch_bounds__(256) void softmax_neg_kernel()
{
    const int b = blockIdx.x;
    const int t = threadIdx.x;
    const unsigned full = 0xffffffffu;

    float4 v = reinterpret_cast<const float4*>(&g_u[(size_t)b * OUTD])[t];

    float mx = v.x; int ai = t*4;
    if (v.y > mx) { mx = v.y; ai = t*4+1; }
    if (v.z > mx) { mx = v.z; ai = t*4+2; }
    if (v.w > mx) { mx = v.w; ai = t*4+3; }

#pragma unroll
    for (int off = 16; off > 0; off >>= 1) {
        float omx = __shfl_down_sync(full, mx, off);
        int   oai = __shfl_down_sync(full, ai, off);
        if (omx > mx || (omx == mx && oai < ai)) { mx = omx; ai = oai; }
    }
    __shared__ float smx[8];
    __shared__ int   sai[8];
    __shared__ float ssum[8];
    const int warp = t >> 5, lane = t & 31;
    if (lane == 0) { smx[warp] = mx; sai[warp] = ai; }
    __syncthreads();
    if (t == 0) {
        for (int w = 1; w < 8; ++w)
            if (smx[w] > smx[0] || (smx[w] == smx[0] && sai[w] < sai[0])) {
                smx[0] = smx[w]; sai[0] = sai[w];
            }
    }
    __syncthreads();
    const float MX = smx[0];
    const int   AI = sai[0];

    float4 e;
    e.x = expf(v.x - MX); e.y = expf(v.y - MX);
    e.z = expf(v.z - MX); e.w = expf(v.w - MX);
    float s = e.x + e.y + e.z + e.w;
#pragma unroll
    for (int off = 16; off > 0; off >>= 1) s += __shfl_down_sync(full, s, off);
    if (lane == 0) ssum[warp] = s;
    __syncthreads();
    if (t == 0) {
        float tot = 0.f;
        for (int w = 0; w < 8; ++w) tot += ssum[w];
        ssum[0] = tot;
    }
    __syncthreads();
    const float inv = 1.f / ssum[0];

    float4 o;
    o.x = (t*4+0 == AI) ? e.x*inv : -e.x*inv;
    o.y = (t*4+1 == AI) ? e.y*inv : -e.y*inv;
    o.z = (t*4+2 == AI) ? e.z*inv : -e.z*inv;
    o.w = (t*4+3 == AI) ? e.w*inv : -e.w*inv;
    reinterpret_cast<float4*>(&g_yn[(size_t)b * OUTD])[t] = o;
}

// ============================================================
// Tiled transpose: src[R][C] -> dst[C][R]
// ============================================================
__global__ __launch_bounds__(256) void transpose_kernel(
    const float* __restrict__ src, float* __restrict__ dst, int R, int C)
{
    __shared__ float tile[32][33];
    const int c0 = blockIdx.x * 32;
    const int r0 = blockIdx.y * 32;
    const int tx = threadIdx.x, ty = threadIdx.y;
#pragma unroll
    for (int i = 0; i < 4; ++i)
        tile[ty + i*8][tx] = src[(size_t)(r0 + ty + i*8) * C + c0 + tx];
    __syncthreads();
#pragma unroll
    for (int i = 0; i < 4; ++i)
        dst[(size_t)(c0 + ty + i*8) * R + r0 + tx] = tile[tx][ty + i*8];
}

// ============================================================
// Adaptive rate: rate[o] = 1e-3 * |1 - ||W[o,:]||_2|^0.5
// ============================================================
__global__ __launch_bounds__(256) void rate_kernel(const float* __restrict__ W)
{
    const int o = blockIdx.x;
    const int t = threadIdx.x;
    const unsigned full = 0xffffffffu;
    float4 w = reinterpret_cast<const float4*>(&W[(size_t)o * IND])[t];
    float s = w.x*w.x + w.y*w.y + w.z*w.z + w.w*w.w;
#pragma unroll
    for (int off = 16; off > 0; off >>= 1) s += __shfl_down_sync(full, s, off);
    __shared__ float ssum[8];
    const int warp = t >> 5, lane = t & 31;
    if (lane == 0) ssum[warp] = s;
    __syncthreads();
    if (t == 0) {
        float tot = 0.f;
        for (int w2 = 0; w2 < 8; ++w2) tot += ssum[w2];
        float norm = sqrtf(tot);
        g_rate[o] = 1e-3f * sqrtf(fabsf(1.f - norm));
    }
}

// ============================================================
// Column reduction: m[o] = mean_b(yn[b,o] * u[b,o])
// ============================================================
__global__ __launch_bounds__(256) void col_partial_kernel()
{
    const int o = blockIdx.x * 256 + threadIdx.x;
    const int c = blockIdx.y;
    const int r0 = c * (BSZ / NCHUNK);
    float acc = 0.f;
#pragma unroll
    for (int r = 0; r < BSZ / NCHUNK; ++r) {
        const size_t off = (size_t)(r0 + r) * OUTD + o;
        acc += g_yn[off] * g_u[off];
    }
    g_P[c * OUTD + o] = acc;
}

__global__ __launch_bounds__(256) void m_final_kernel()
{
    const int o = blockIdx.x * 256 + threadIdx.x;
    float acc = 0.f;
    for (int c = 0; c < NCHUNK; ++c) acc += g_P[c * OUTD + o];
    g_m[o] = acc * (1.f / (float)BSZ);
}

// ============================================================
// Epilogue: out[o,i] = rate[o] * (sum_s S[s][o,i]/B - m[o]*W[o,i])
// ============================================================
__global__ __launch_bounds__(256) void epilogue_kernel(
    const float* __restrict__ W, float* __restrict__ out)
{
    const int o = blockIdx.x;
    const int t = threadIdx.x;
    const float m = g_m[o];
    const float r = g_rate[o];
    float4 wv = reinterpret_cast<const float4*>(&W[(size_t)o * IND])[t];
    float4 s = make_float4(0.f, 0.f, 0.f, 0.f);
#pragma unroll
    for (int sp = 0; sp < NSPLIT; ++sp) {
        float4 p = reinterpret_cast<const float4*>(
            &g_S[(size_t)sp * OUTD * IND + (size_t)o * IND])[t];
        s.x += p.x; s.y += p.y; s.z += p.z; s.w += p.w;
    }
    const float invB = 1.f / (float)BSZ;
    float4 ov;
    ov.x = r * (s.x * invB - m * wv.x);
    ov.y = r * (s.y * invB - m * wv.y);
    ov.z = r * (s.z * invB - m * wv.z);
    ov.w = r * (s.w * invB - m * wv.w);
    reinterpret_cast<float4*>(&out[(size_t)o * IND])[t] = ov;
}

// ============================================================
extern "C" void kernel_launch(void* const* d_in, const int* in_sizes, int n_in,
                              void* d_out, int out_size)
{
    const float* x = (const float*)d_in[0];   // [8192, 1024]
    const float* W = (const float*)d_in[1];   // [1024, 1024]
    const float* b = (const float*)d_in[2];   // [1024]
    float* out = (float*)d_out;               // [1024, 1024]

    cudaFuncSetAttribute(gemm_tf32x3_kernel,
                         cudaFuncAttributeMaxDynamicSharedMemorySize, SMEM_BYTES);

    float* g_u_p;   cudaGetSymbolAddress((void**)&g_u_p,   g_u);
    float* g_yn_p;  cudaGetSymbolAddress((void**)&g_yn_p,  g_yn);
    float* g_xT_p;  cudaGetSymbolAddress((void**)&g_xT_p,  g_xT);
    float* g_ynT_p; cudaGetSymbolAddress((void**)&g_ynT_p, g_ynT);
    float* g_S_p;   cudaGetSymbolAddress((void**)&g_S_p,   g_S);

    // u = x @ W^T + b   (tf32x3 mma.sync)
    gemm_tf32x3_kernel<<<dim3(OUTD/128, BSZ/128, 1), 256, SMEM_BYTES>>>(
        x, IND, W, IND, 0, g_u_p, OUTD, 0, b);
    // yn = negate_non_maximal(softmax(u))
    softmax_neg_kernel<<<BSZ, 256>>>();
    // transposes for GEMM2 (K-major operands)
    transpose_kernel<<<dim3(IND/32, BSZ/32), dim3(32, 8)>>>(x, g_xT_p, BSZ, IND);
    transpose_kernel<<<dim3(OUTD/32, BSZ/32), dim3(32, 8)>>>(g_yn_p, g_ynT_p, BSZ, OUTD);
    // per-row rate + m[o]
    rate_kernel<<<OUTD, 256>>>(W);
    col_partial_kernel<<<dim3(OUTD/256, NCHUNK), 256>>>();
    m_final_kernel<<<OUTD/256, 256>>>();
    // S[z] = yn^T @ x partials  (tf32x3 mma.sync, split-K = 8)
    gemm_tf32x3_kernel<<<dim3(IND/128, OUTD/128, NSPLIT), 256, SMEM_BYTES>>>(
        g_ynT_p, BSZ, g_xT_p, BSZ, BSZ/NSPLIT, g_S_p, IND,
        (size_t)OUTD * IND, nullptr);
    // out = rate * (sum S / B - m*W)
    epilogue_kernel<<<OUTD, 256>>>(W, out);
}

// round 6
// speedup vs baseline: 2.0330x; 1.5926x over previous
#include <cuda_runtime.h>
#include <cstdint>
#include <math.h>

#define BSZ   8192
#define IND   1024
#define OUTD  1024
#define NSPLIT 8
#define NCHUNK 512

// ---- scratch (static device globals; no dynamic allocation) ----
__device__ float g_u  [(size_t)BSZ * OUTD];          // 32 MB
__device__ float g_yn [(size_t)BSZ * OUTD];          // 32 MB
__device__ float g_xT [(size_t)IND * BSZ];           // 32 MB  x^T  [i][b]
__device__ float g_ynT[(size_t)OUTD * BSZ];          // 32 MB  yn^T [o][b]
__device__ float g_P  [NCHUNK * OUTD];               // partial column sums
__device__ float g_m  [OUTD];
__device__ float g_rate[OUTD];
__device__ float g_S  [(size_t)NSPLIT * OUTD * IND]; // 32 MB split-K partials

// bf16x2 rn pack: lower half <- lo, upper half <- hi
__device__ __forceinline__ uint32_t bf16x2_rn(float hi, float lo) {
    uint32_t r;
    asm("cvt.rn.bf16x2.f32 %0, %1, %2;" : "=r"(r) : "f"(hi), "f"(lo));
    return r;
}

__device__ __forceinline__ void mma_bf16_k16(float c[4], const uint32_t a[4],
                                             const uint32_t b[2])
{
    asm volatile(
        "mma.sync.aligned.m16n8k16.row.col.f32.bf16.bf16.f32 "
        "{%0,%1,%2,%3}, {%4,%5,%6,%7}, {%8,%9}, {%0,%1,%2,%3};\n"
        : "+f"(c[0]), "+f"(c[1]), "+f"(c[2]), "+f"(c[3])
        : "r"(a[0]), "r"(a[1]), "r"(a[2]), "r"(a[3]),
          "r"(b[0]), "r"(b[1]));
}

// Stage: 128 rows x 64 k (bf16), row stride 72 bf16 (=36 words, conflict-free)
#define ST_BF16 72
#define TILE_HW (128 * ST_BF16)              // bf16 elements per buffer
#define SMEM_BYTES (4 * TILE_HW * 2)         // Ahi, Alo, Bhi, Blo = 73728 B

// ============================================================
// bf16x3 mma.sync GEMM: D[m0+r][n0+c] = sum_k A[m][k]*B[n][k] (+bias[n])
// A: [Mtot][lda] K-major fp32, B: [Ntot][ldb] K-major fp32.
// CTA 128x128, 8 warps (2M x 4N), warp tile 64x32, stage K = 64.
// Split: hi = trunc-bf16(v), lo = rn-bf16(v - hi); passes hh + hl + lh.
// ============================================================
__global__ __launch_bounds__(256, 2) void gemm_bf16x3_kernel(
    const float* __restrict__ A, int lda,
    const float* __restrict__ B, int ldb,
    int kzstep, float* __restrict__ dstBase, int ldd, size_t zstride,
    const float* __restrict__ bias, int nstages)
{
    extern __shared__ uint16_t smem_h[];
    uint16_t* sAhi = smem_h;
    uint16_t* sAlo = smem_h + TILE_HW;
    uint16_t* sBhi = smem_h + 2 * TILE_HW;
    uint16_t* sBlo = smem_h + 3 * TILE_HW;

    const int t     = threadIdx.x;
    const int lane  = t & 31;
    const int warp  = t >> 5;
    const int warpM = warp & 1;   // 0..1
    const int warpN = warp >> 1;  // 0..3
    const int m0    = blockIdx.y * 128;
    const int n0    = blockIdx.x * 128;
    const int kbase = blockIdx.z * kzstep;
    float* dst = dstBase + (size_t)blockIdx.z * zstride;

    const int gr = lane >> 2;     // 0..7
    const int kc = lane & 3;      // 0..3

    float c[4][4][4];
#pragma unroll
    for (int mt = 0; mt < 4; ++mt)
#pragma unroll
        for (int nt = 0; nt < 4; ++nt)
#pragma unroll
            for (int e = 0; e < 4; ++e) c[mt][nt][e] = 0.f;

    const int frow0 = t >> 4;          // 0..15 (+16 per j)
    const int fk4   = (t & 15) * 4;    // k offset 0..60

    const uint32_t* pAh = reinterpret_cast<const uint32_t*>(sAhi);
    const uint32_t* pAl = reinterpret_cast<const uint32_t*>(sAlo);
    const uint32_t* pBh = reinterpret_cast<const uint32_t*>(sBhi);
    const uint32_t* pBl = reinterpret_cast<const uint32_t*>(sBlo);

    for (int s = 0; s < nstages; ++s) {
        const int ks0 = kbase + s * 64;
        __syncthreads();
#pragma unroll
        for (int j = 0; j < 8; ++j) {
            const int row = frow0 + 16 * j;
            const int wo  = row * (ST_BF16 / 2) + fk4 / 2;   // b32 word offset

            float4 va = *reinterpret_cast<const float4*>(
                &A[(size_t)(m0 + row) * lda + ks0 + fk4]);
            {
                uint32_t x0 = __float_as_uint(va.x), x1 = __float_as_uint(va.y);
                uint32_t x2 = __float_as_uint(va.z), x3 = __float_as_uint(va.w);
                uint32_t h01 = __byte_perm(x0, x1, 0x7632);
                uint32_t h23 = __byte_perm(x2, x3, 0x7632);
                float l0 = va.x - __uint_as_float(x0 & 0xFFFF0000u);
                float l1 = va.y - __uint_as_float(x1 & 0xFFFF0000u);
                float l2 = va.z - __uint_as_float(x2 & 0xFFFF0000u);
                float l3 = va.w - __uint_as_float(x3 & 0xFFFF0000u);
                uint32_t lo01 = bf16x2_rn(l1, l0);
                uint32_t lo23 = bf16x2_rn(l3, l2);
                *reinterpret_cast<uint2*>(
                    reinterpret_cast<uint32_t*>(sAhi) + wo) = make_uint2(h01, h23);
                *reinterpret_cast<uint2*>(
                    reinterpret_cast<uint32_t*>(sAlo) + wo) = make_uint2(lo01, lo23);
            }
            float4 vb = *reinterpret_cast<const float4*>(
                &B[(size_t)(n0 + row) * ldb + ks0 + fk4]);
            {
                uint32_t x0 = __float_as_uint(vb.x), x1 = __float_as_uint(vb.y);
                uint32_t x2 = __float_as_uint(vb.z), x3 = __float_as_uint(vb.w);
                uint32_t h01 = __byte_perm(x0, x1, 0x7632);
                uint32_t h23 = __byte_perm(x2, x3, 0x7632);
                float l0 = vb.x - __uint_as_float(x0 & 0xFFFF0000u);
                float l1 = vb.y - __uint_as_float(x1 & 0xFFFF0000u);
                float l2 = vb.z - __uint_as_float(x2 & 0xFFFF0000u);
                float l3 = vb.w - __uint_as_float(x3 & 0xFFFF0000u);
                uint32_t lo01 = bf16x2_rn(l1, l0);
                uint32_t lo23 = bf16x2_rn(l3, l2);
                *reinterpret_cast<uint2*>(
                    reinterpret_cast<uint32_t*>(sBhi) + wo) = make_uint2(h01, h23);
                *reinterpret_cast<uint2*>(
                    reinterpret_cast<uint32_t*>(sBlo) + wo) = make_uint2(lo01, lo23);
            }
        }
        __syncthreads();

#pragma unroll
        for (int ks = 0; ks < 4; ++ks) {
            const int k0 = ks * 8 + kc;    // b32 word within row (36 words)
            uint32_t ah[4][4], bh[4][2];

#pragma unroll
            for (int mt = 0; mt < 4; ++mt) {
                const int r = warpM * 64 + mt * 16 + gr;
                ah[mt][0] = pAh[r * 36 + k0];
                ah[mt][1] = pAh[(r + 8) * 36 + k0];
                ah[mt][2] = pAh[r * 36 + k0 + 4];
                ah[mt][3] = pAh[(r + 8) * 36 + k0 + 4];
            }
#pragma unroll
            for (int nt = 0; nt < 4; ++nt) {
                const int n = warpN * 32 + nt * 8 + gr;
                bh[nt][0] = pBh[n * 36 + k0];
                bh[nt][1] = pBh[n * 36 + k0 + 4];
            }
            // hi * hi
#pragma unroll
            for (int mt = 0; mt < 4; ++mt)
#pragma unroll
                for (int nt = 0; nt < 4; ++nt)
                    mma_bf16_k16(c[mt][nt], ah[mt], bh[nt]);

            // hi * lo
            {
                uint32_t bl[4][2];
#pragma unroll
                for (int nt = 0; nt < 4; ++nt) {
                    const int n = warpN * 32 + nt * 8 + gr;
                    bl[nt][0] = pBl[n * 36 + k0];
                    bl[nt][1] = pBl[n * 36 + k0 + 4];
                }
#pragma unroll
                for (int mt = 0; mt < 4; ++mt)
#pragma unroll
                    for (int nt = 0; nt < 4; ++nt)
                        mma_bf16_k16(c[mt][nt], ah[mt], bl[nt]);
            }
            // lo * hi
            {
                uint32_t al[4][4];
#pragma unroll
                for (int mt = 0; mt < 4; ++mt) {
                    const int r = warpM * 64 + mt * 16 + gr;
                    al[mt][0] = pAl[r * 36 + k0];
                    al[mt][1] = pAl[(r + 8) * 36 + k0];
                    al[mt][2] = pAl[r * 36 + k0 + 4];
                    al[mt][3] = pAl[(r + 8) * 36 + k0 + 4];
                }
#pragma unroll
                for (int mt = 0; mt < 4; ++mt)
#pragma unroll
                    for (int nt = 0; nt < 4; ++nt)
                        mma_bf16_k16(c[mt][nt], al[mt], bh[nt]);
            }
        }
    }

    // ---- epilogue: C regs -> global (float2 per half-tile) ----
#pragma unroll
    for (int mt = 0; mt < 4; ++mt) {
        const int r = m0 + warpM * 64 + mt * 16 + gr;
#pragma unroll
        for (int nt = 0; nt < 4; ++nt) {
            const int cc = n0 + warpN * 32 + nt * 8 + (lane & 3) * 2;
            float2 v0 = make_float2(c[mt][nt][0], c[mt][nt][1]);
            float2 v1 = make_float2(c[mt][nt][2], c[mt][nt][3]);
            if (bias) {
                const float b0 = __ldg(&bias[cc]);
                const float b1 = __ldg(&bias[cc + 1]);
                v0.x += b0; v0.y += b1;
                v1.x += b0; v1.y += b1;
            }
            *reinterpret_cast<float2*>(&dst[(size_t)r * ldd + cc])       = v0;
            *reinterpret_cast<float2*>(&dst[(size_t)(r + 8) * ldd + cc]) = v1;
        }
    }
}

// ============================================================
// Per-row softmax + negate-non-maximal: yn[b,:] from u[b,:]
// ============================================================
__global__ __launch_bounds__(256) void softmax_neg_kernel()
{
    const int b = blockIdx.x;
    const int t = threadIdx.x;
    const unsigned full = 0xffffffffu;

    float4 v = reinterpret_cast<const float4*>(&g_u[(size_t)b * OUTD])[t];

    float mx = v.x; int ai = t*4;
    if (v.y > mx) { mx = v.y; ai = t*4+1; }
    if (v.z > mx) { mx = v.z; ai = t*4+2; }
    if (v.w > mx) { mx = v.w; ai = t*4+3; }

#pragma unroll
    for (int off = 16; off > 0; off >>= 1) {
        float omx = __shfl_down_sync(full, mx, off);
        int   oai = __shfl_down_sync(full, ai, off);
        if (omx > mx || (omx == mx && oai < ai)) { mx = omx; ai = oai; }
    }
    __shared__ float smx[8];
    __shared__ int   sai[8];
    __shared__ float ssum[8];
    const int warp = t >> 5, lane = t & 31;
    if (lane == 0) { smx[warp] = mx; sai[warp] = ai; }
    __syncthreads();
    if (t == 0) {
        for (int w = 1; w < 8; ++w)
            if (smx[w] > smx[0] || (smx[w] == smx[0] && sai[w] < sai[0])) {
                smx[0] = smx[w]; sai[0] = sai[w];
            }
    }
    __syncthreads();
    const float MX = smx[0];
    const int   AI = sai[0];

    float4 e;
    e.x = expf(v.x - MX); e.y = expf(v.y - MX);
    e.z = expf(v.z - MX); e.w = expf(v.w - MX);
    float s = e.x + e.y + e.z + e.w;
#pragma unroll
    for (int off = 16; off > 0; off >>= 1) s += __shfl_down_sync(full, s, off);
    if (lane == 0) ssum[warp] = s;
    __syncthreads();
    if (t == 0) {
        float tot = 0.f;
        for (int w = 0; w < 8; ++w) tot += ssum[w];
        ssum[0] = tot;
    }
    __syncthreads();
    const float inv = 1.f / ssum[0];

    float4 o;
    o.x = (t*4+0 == AI) ? e.x*inv : -e.x*inv;
    o.y = (t*4+1 == AI) ? e.y*inv : -e.y*inv;
    o.z = (t*4+2 == AI) ? e.z*inv : -e.z*inv;
    o.w = (t*4+3 == AI) ? e.w*inv : -e.w*inv;
    reinterpret_cast<float4*>(&g_yn[(size_t)b * OUTD])[t] = o;
}

// ============================================================
// Tiled transpose: src[R][C] -> dst[C][R]
// ============================================================
__global__ __launch_bounds__(256) void transpose_kernel(
    const float* __restrict__ src, float* __restrict__ dst, int R, int C)
{
    __shared__ float tile[32][33];
    const int c0 = blockIdx.x * 32;
    const int r0 = blockIdx.y * 32;
    const int tx = threadIdx.x, ty = threadIdx.y;
#pragma unroll
    for (int i = 0; i < 4; ++i)
        tile[ty + i*8][tx] = src[(size_t)(r0 + ty + i*8) * C + c0 + tx];
    __syncthreads();
#pragma unroll
    for (int i = 0; i < 4; ++i)
        dst[(size_t)(c0 + ty + i*8) * R + r0 + tx] = tile[tx][ty + i*8];
}

// ============================================================
// Adaptive rate: rate[o] = 1e-3 * |1 - ||W[o,:]||_2|^0.5
// ============================================================
__global__ __launch_bounds__(256) void rate_kernel(const float* __restrict__ W)
{
    const int o = blockIdx.x;
    const int t = threadIdx.x;
    const unsigned full = 0xffffffffu;
    float4 w = reinterpret_cast<const float4*>(&W[(size_t)o * IND])[t];
    float s = w.x*w.x + w.y*w.y + w.z*w.z + w.w*w.w;
#pragma unroll
    for (int off = 16; off > 0; off >>= 1) s += __shfl_down_sync(full, s, off);
    __shared__ float ssum[8];
    const int warp = t >> 5, lane = t & 31;
    if (lane == 0) ssum[warp] = s;
    __syncthreads();
    if (t == 0) {
        float tot = 0.f;
        for (int w2 = 0; w2 < 8; ++w2) tot += ssum[w2];
        float norm = sqrtf(tot);
        g_rate[o] = 1e-3f * sqrtf(fabsf(1.f - norm));
    }
}

// ============================================================
// Column reduction: m[o] = mean_b(yn[b,o] * u[b,o])
// ============================================================
__global__ __launch_bounds__(256) void col_partial_kernel()
{
    const int o = blockIdx.x * 256 + threadIdx.x;
    const int c = blockIdx.y;
    const int r0 = c * (BSZ / NCHUNK);
    float acc = 0.f;
#pragma unroll
    for (int r = 0; r < BSZ / NCHUNK; ++r) {
        const size_t off = (size_t)(r0 + r) * OUTD + o;
        acc += g_yn[off] * g_u[off];
    }
    g_P[c * OUTD + o] = acc;
}

__global__ __launch_bounds__(256) void m_final_kernel()
{
    const int o = blockIdx.x * 256 + threadIdx.x;
    float acc = 0.f;
    for (int c = 0; c < NCHUNK; ++c) acc += g_P[c * OUTD + o];
    g_m[o] = acc * (1.f / (float)BSZ);
}

// ============================================================
// Epilogue: out[o,i] = rate[o] * (sum_s S[s][o,i]/B - m[o]*W[o,i])
// ============================================================
__global__ __launch_bounds__(256) void epilogue_kernel(
    const float* __restrict__ W, float* __restrict__ out)
{
    const int o = blockIdx.x;
    const int t = threadIdx.x;
    const float m = g_m[o];
    const float r = g_rate[o];
    float4 wv = reinterpret_cast<const float4*>(&W[(size_t)o * IND])[t];
    float4 s = make_float4(0.f, 0.f, 0.f, 0.f);
#pragma unroll
    for (int sp = 0; sp < NSPLIT; ++sp) {
        float4 p = reinterpret_cast<const float4*>(
            &g_S[(size_t)sp * OUTD * IND + (size_t)o * IND])[t];
        s.x += p.x; s.y += p.y; s.z += p.z; s.w += p.w;
    }
    const float invB = 1.f / (float)BSZ;
    float4 ov;
    ov.x = r * (s.x * invB - m * wv.x);
    ov.y = r * (s.y * invB - m * wv.y);
    ov.z = r * (s.z * invB - m * wv.z);
    ov.w = r * (s.w * invB - m * wv.w);
    reinterpret_cast<float4*>(&out[(size_t)o * IND])[t] = ov;
}

// ============================================================
extern "C" void kernel_launch(void* const* d_in, const int* in_sizes, int n_in,
                              void* d_out, int out_size)
{
    const float* x = (const float*)d_in[0];   // [8192, 1024]
    const float* W = (const float*)d_in[1];   // [1024, 1024]
    const float* b = (const float*)d_in[2];   // [1024]
    float* out = (float*)d_out;               // [1024, 1024]

    cudaFuncSetAttribute(gemm_bf16x3_kernel,
                         cudaFuncAttributeMaxDynamicSharedMemorySize, SMEM_BYTES);

    float* g_u_p;   cudaGetSymbolAddress((void**)&g_u_p,   g_u);
    float* g_yn_p;  cudaGetSymbolAddress((void**)&g_yn_p,  g_yn);
    float* g_xT_p;  cudaGetSymbolAddress((void**)&g_xT_p,  g_xT);
    float* g_ynT_p; cudaGetSymbolAddress((void**)&g_ynT_p, g_ynT);
    float* g_S_p;   cudaGetSymbolAddress((void**)&g_S_p,   g_S);

    // u = x @ W^T + b   (bf16x3 mma.sync, K=1024 -> 16 stages)
    gemm_bf16x3_kernel<<<dim3(OUTD/128, BSZ/128, 1), 256, SMEM_BYTES>>>(
        x, IND, W, IND, 0, g_u_p, OUTD, 0, b, IND / 64);
    // yn = negate_non_maximal(softmax(u))
    softmax_neg_kernel<<<BSZ, 256>>>();
    // transposes for GEMM2 (K-major operands)
    transpose_kernel<<<dim3(IND/32, BSZ/32), dim3(32, 8)>>>(x, g_xT_p, BSZ, IND);
    transpose_kernel<<<dim3(OUTD/32, BSZ/32), dim3(32, 8)>>>(g_yn_p, g_ynT_p, BSZ, OUTD);
    // per-row rate + m[o]
    rate_kernel<<<OUTD, 256>>>(W);
    col_partial_kernel<<<dim3(OUTD/256, NCHUNK), 256>>>();
    m_final_kernel<<<OUTD/256, 256>>>();
    // S[z] = yn^T @ x partials  (bf16x3 mma.sync, split-K = 8, 16 stages each)
    gemm_bf16x3_kernel<<<dim3(IND/128, OUTD/128, NSPLIT), 256, SMEM_BYTES>>>(
        g_ynT_p, BSZ, g_xT_p, BSZ, BSZ/NSPLIT, g_S_p, IND,
        (size_t)OUTD * IND, nullptr, (BSZ/NSPLIT) / 64);
    // out = rate * (sum S / B - m*W)
    epilogue_kernel<<<OUTD, 256>>>(W, out);
}

// round 7
// speedup vs baseline: 2.1354x; 1.0503x over previous
#include <cuda_runtime.h>
#include <cstdint>
#include <math.h>

#define BSZ   8192
#define IND   1024
#define OUTD  1024
#define NSPLIT 8
#define NCHUNK 512

// ---- scratch (static device globals; no dynamic allocation) ----
__device__ float    g_u  [(size_t)BSZ * OUTD];           // 32 MB
__device__ float    g_yn [(size_t)BSZ * OUTD];           // 32 MB
__device__ float    g_P  [NCHUNK * OUTD];
__device__ float    g_m  [OUTD];
__device__ float    g_rate[OUTD];
__device__ float    g_S  [(size_t)NSPLIT * OUTD * IND];  // 32 MB
// pre-split bf16 operands
__device__ uint16_t g_xh [(size_t)BSZ * IND];            // x hi
__device__ uint16_t g_xl [(size_t)BSZ * IND];            // x lo
__device__ uint16_t g_Wh [(size_t)OUTD * IND];
__device__ uint16_t g_Wl [(size_t)OUTD * IND];
__device__ uint16_t g_xTh[(size_t)IND * BSZ];            // x^T hi
__device__ uint16_t g_xTl[(size_t)IND * BSZ];
__device__ uint16_t g_ynTh[(size_t)OUTD * BSZ];          // yn^T hi
__device__ uint16_t g_ynTl[(size_t)OUTD * BSZ];

// ============================================================
// helpers
// ============================================================
__device__ __forceinline__ uint32_t bf16x2_rn(float hi, float lo) {
    uint32_t r;
    asm("cvt.rn.bf16x2.f32 %0, %1, %2;" : "=r"(r) : "f"(hi), "f"(lo));
    return r;
}
__device__ __forceinline__ void mma_bf16_k16(float c[4], const uint32_t a[4],
                                             const uint32_t b[2])
{
    asm volatile(
        "mma.sync.aligned.m16n8k16.row.col.f32.bf16.bf16.f32 "
        "{%0,%1,%2,%3}, {%4,%5,%6,%7}, {%8,%9}, {%0,%1,%2,%3};\n"
        : "+f"(c[0]), "+f"(c[1]), "+f"(c[2]), "+f"(c[3])
        : "r"(a[0]), "r"(a[1]), "r"(a[2]), "r"(a[3]),
          "r"(b[0]), "r"(b[1]));
}
__device__ __forceinline__ void ldsm_x4(uint32_t r[4], uint32_t addr) {
    asm volatile("ldmatrix.sync.aligned.m8n8.x4.shared.b16 {%0,%1,%2,%3}, [%4];"
        : "=r"(r[0]), "=r"(r[1]), "=r"(r[2]), "=r"(r[3]) : "r"(addr));
}
#define CP_ASYNC16(saddr, gptr) \
    asm volatile("cp.async.cg.shared.global [%0], [%1], 16;" \
        :: "r"(saddr), "l"(gptr))
#define CP_COMMIT()  asm volatile("cp.async.commit_group;")
#define CP_WAIT(n)   asm volatile("cp.async.wait_group %0;" :: "n"(n))

// Stage geometry: K=32 bf16 per stage, 128 rows, row stride 40 bf16 (80 B)
#define BK      32
#define STRIDE  40
#define BUF_HW  (128 * STRIDE)          // 5120 bf16 per buffer
#define STAGE_B (4 * BUF_HW * 2)        // Ah, Al, Bh, Bl = 40960 B
#define SMEM_BYTES (2 * STAGE_B)        // double buffered = 81920 B

__device__ __forceinline__ void fill_stage(
    uint32_t sbase, int t,
    const uint16_t* __restrict__ Ah, const uint16_t* __restrict__ Al, int lda,
    const uint16_t* __restrict__ Bh, const uint16_t* __restrict__ Bl, int ldb,
    int m0, int n0, int ks0)
{
#pragma unroll
    for (int i = 0; i < 8; ++i) {
        const int buf = i >> 1;
        const int c   = t + 256 * (i & 1);
        const int row = c >> 2;
        const int c16 = c & 3;
        const uint16_t* g;
        int base0, ld;
        if (buf == 0)      { g = Ah; base0 = m0; ld = lda; }
        else if (buf == 1) { g = Al; base0 = m0; ld = lda; }
        else if (buf == 2) { g = Bh; base0 = n0; ld = ldb; }
        else               { g = Bl; base0 = n0; ld = ldb; }
        const uint16_t* gp = g + (size_t)(base0 + row) * ld + ks0 + c16 * 8;
        const uint32_t sa = sbase +
            (uint32_t)((buf * BUF_HW + row * STRIDE + c16 * 8) * 2);
        CP_ASYNC16(sa, gp);
    }
}

// ============================================================
// bf16x3 pipelined mma.sync GEMM.
// D[m0+r][n0+c] = sum_k A[m][k]*B[n][k] (+bias[n]); A,B pre-split bf16 K-major.
// CTA 128x128, 8 warps (2M x 4N), warp tile 64x32, stage K=32, double buffer.
// ============================================================
__global__ __launch_bounds__(256, 2) void gemm_bf16v2_kernel(
    const uint16_t* __restrict__ Ah, const uint16_t* __restrict__ Al, int lda,
    const uint16_t* __restrict__ Bh, const uint16_t* __restrict__ Bl, int ldb,
    int kzstep, float* __restrict__ dstBase, int ldd, size_t zstride,
    const float* __restrict__ bias, int nstages)
{
    extern __shared__ uint16_t sm[];
    const uint32_t sbase0 = (uint32_t)__cvta_generic_to_shared(sm);

    const int t     = threadIdx.x;
    const int lane  = t & 31;
    const int warp  = t >> 5;
    const int warpM = warp & 1;
    const int warpN = warp >> 1;
    const int m0    = blockIdx.y * 128;
    const int n0    = blockIdx.x * 128;
    const int kbase = blockIdx.z * kzstep;
    float* dst = dstBase + (size_t)blockIdx.z * zstride;

    const int gr = lane >> 2;
    const int la15 = lane & 15;
    const int lhi  = lane >> 4;

    // fragment ldmatrix byte offsets (within a buffer)
    uint32_t aoff[4], boff[2];
#pragma unroll
    for (int mt = 0; mt < 4; ++mt)
        aoff[mt] = (uint32_t)(((warpM * 64 + mt * 16 + la15) * STRIDE
                               + lhi * 8) * 2);
#pragma unroll
    for (int p = 0; p < 2; ++p)
        boff[p] = (uint32_t)(((warpN * 32 + p * 16 + lhi * 8 + (lane & 7))
                               * STRIDE + ((lane >> 3) & 1) * 8) * 2);

    float c[4][4][4];
#pragma unroll
    for (int mt = 0; mt < 4; ++mt)
#pragma unroll
        for (int nt = 0; nt < 4; ++nt)
#pragma unroll
            for (int e = 0; e < 4; ++e) c[mt][nt][e] = 0.f;

    // prologue
    fill_stage(sbase0, t, Ah, Al, lda, Bh, Bl, ldb, m0, n0, kbase);
    CP_COMMIT();

    for (int s = 0; s < nstages; ++s) {
        if (s + 1 < nstages) {
            fill_stage(sbase0 + ((s + 1) & 1) * STAGE_B, t,
                       Ah, Al, lda, Bh, Bl, ldb, m0, n0,
                       kbase + (s + 1) * BK);
            CP_COMMIT();
            CP_WAIT(1);
        } else {
            CP_WAIT(0);
        }
        __syncthreads();

        const uint32_t sb  = sbase0 + (s & 1) * STAGE_B;
        const uint32_t sAh = sb;
        const uint32_t sAl = sb + BUF_HW * 2;
        const uint32_t sBh = sb + 2 * BUF_HW * 2;
        const uint32_t sBl = sb + 3 * BUF_HW * 2;

#pragma unroll
        for (int ks = 0; ks < 2; ++ks) {
            const uint32_t ko = (uint32_t)(ks * 32);   // 16 bf16 = 32 B
            uint32_t ah[4][4], bb[4][2], t4[4];

#pragma unroll
            for (int mt = 0; mt < 4; ++mt)
                ldsm_x4(ah[mt], sAh + aoff[mt] + ko);
#pragma unroll
            for (int p = 0; p < 2; ++p) {
                ldsm_x4(t4, sBh + boff[p] + ko);
                bb[2*p][0] = t4[0]; bb[2*p][1] = t4[1];
                bb[2*p+1][0] = t4[2]; bb[2*p+1][1] = t4[3];
            }
            // hi * hi
#pragma unroll
            for (int mt = 0; mt < 4; ++mt)
#pragma unroll
                for (int nt = 0; nt < 4; ++nt)
                    mma_bf16_k16(c[mt][nt], ah[mt], bb[nt]);

            // hi * lo
            {
                uint32_t bl[4][2];
#pragma unroll
                for (int p = 0; p < 2; ++p) {
                    ldsm_x4(t4, sBl + boff[p] + ko);
                    bl[2*p][0] = t4[0]; bl[2*p][1] = t4[1];
                    bl[2*p+1][0] = t4[2]; bl[2*p+1][1] = t4[3];
                }
#pragma unroll
                for (int mt = 0; mt < 4; ++mt)
#pragma unroll
                    for (int nt = 0; nt < 4; ++nt)
                        mma_bf16_k16(c[mt][nt], ah[mt], bl[nt]);
            }
            // lo * hi
            {
                uint32_t al[4][4];
#pragma unroll
                for (int mt = 0; mt < 4; ++mt)
                    ldsm_x4(al[mt], sAl + aoff[mt] + ko);
#pragma unroll
                for (int mt = 0; mt < 4; ++mt)
#pragma unroll
                    for (int nt = 0; nt < 4; ++nt)
                        mma_bf16_k16(c[mt][nt], al[mt], bb[nt]);
            }
        }
        __syncthreads();
    }

    // ---- epilogue ----
#pragma unroll
    for (int mt = 0; mt < 4; ++mt) {
        const int r = m0 + warpM * 64 + mt * 16 + gr;
#pragma unroll
        for (int nt = 0; nt < 4; ++nt) {
            const int cc = n0 + warpN * 32 + nt * 8 + (lane & 3) * 2;
            float2 v0 = make_float2(c[mt][nt][0], c[mt][nt][1]);
            float2 v1 = make_float2(c[mt][nt][2], c[mt][nt][3]);
            if (bias) {
                const float b0 = __ldg(&bias[cc]);
                const float b1 = __ldg(&bias[cc + 1]);
                v0.x += b0; v0.y += b1;
                v1.x += b0; v1.y += b1;
            }
            *reinterpret_cast<float2*>(&dst[(size_t)r * ldd + cc])       = v0;
            *reinterpret_cast<float2*>(&dst[(size_t)(r + 8) * ldd + cc]) = v1;
        }
    }
}

// ============================================================
// Elementwise split: v -> hi = trunc-bf16(v), lo = rn-bf16(v - hi)
// ============================================================
__global__ __launch_bounds__(256) void split_kernel(
    const float* __restrict__ src, uint16_t* __restrict__ dh,
    uint16_t* __restrict__ dl, int n4)
{
    const int i = blockIdx.x * 256 + threadIdx.x;
    if (i >= n4) return;
    float4 v = reinterpret_cast<const float4*>(src)[i];
    uint32_t x0 = __float_as_uint(v.x), x1 = __float_as_uint(v.y);
    uint32_t x2 = __float_as_uint(v.z), x3 = __float_as_uint(v.w);
    uint32_t h01 = __byte_perm(x0, x1, 0x7632);
    uint32_t h23 = __byte_perm(x2, x3, 0x7632);
    float l0 = v.x - __uint_as_float(x0 & 0xFFFF0000u);
    float l1 = v.y - __uint_as_float(x1 & 0xFFFF0000u);
    float l2 = v.z - __uint_as_float(x2 & 0xFFFF0000u);
    float l3 = v.w - __uint_as_float(x3 & 0xFFFF0000u);
    reinterpret_cast<uint2*>(dh)[i] = make_uint2(h01, h23);
    reinterpret_cast<uint2*>(dl)[i] =
        make_uint2(bf16x2_rn(l1, l0), bf16x2_rn(l3, l2));
}

// ============================================================
// Transpose + split: src fp32 [R][C] -> dsthi/dstlo bf16 [C][R]
// ============================================================
__global__ __launch_bounds__(256) void transpose_split_kernel(
    const float* __restrict__ src, uint16_t* __restrict__ dh,
    uint16_t* __restrict__ dl, int R, int C)
{
    __shared__ float tile[32][33];
    const int c0 = blockIdx.x * 32;
    const int r0 = blockIdx.y * 32;
    const int tx = threadIdx.x, ty = threadIdx.y;
#pragma unroll
    for (int i = 0; i < 4; ++i)
        tile[ty + i*8][tx] = src[(size_t)(r0 + ty + i*8) * C + c0 + tx];
    __syncthreads();
#pragma unroll
    for (int i = 0; i < 4; ++i) {
        float v = tile[tx][ty + i*8];
        uint32_t u = __float_as_uint(v);
        uint16_t hi = (uint16_t)(u >> 16);
        float lo = v - __uint_as_float(u & 0xFFFF0000u);
        uint32_t lop = bf16x2_rn(lo, lo);
        const size_t o = (size_t)(c0 + ty + i*8) * R + r0 + tx;
        dh[o] = hi;
        dl[o] = (uint16_t)(lop & 0xFFFF);
    }
}

// ============================================================
// Per-row softmax + negate-non-maximal
// ============================================================
__global__ __launch_bounds__(256) void softmax_neg_kernel()
{
    const int b = blockIdx.x;
    const int t = threadIdx.x;
    const unsigned full = 0xffffffffu;

    float4 v = reinterpret_cast<const float4*>(&g_u[(size_t)b * OUTD])[t];

    float mx = v.x; int ai = t*4;
    if (v.y > mx) { mx = v.y; ai = t*4+1; }
    if (v.z > mx) { mx = v.z; ai = t*4+2; }
    if (v.w > mx) { mx = v.w; ai = t*4+3; }

#pragma unroll
    for (int off = 16; off > 0; off >>= 1) {
        float omx = __shfl_down_sync(full, mx, off);
        int   oai = __shfl_down_sync(full, ai, off);
        if (omx > mx || (omx == mx && oai < ai)) { mx = omx; ai = oai; }
    }
    __shared__ float smx[8];
    __shared__ int   sai[8];
    __shared__ float ssum[8];
    const int warp = t >> 5, lane = t & 31;
    if (lane == 0) { smx[warp] = mx; sai[warp] = ai; }
    __syncthreads();
    if (t == 0) {
        for (int w = 1; w < 8; ++w)
            if (smx[w] > smx[0] || (smx[w] == smx[0] && sai[w] < sai[0])) {
                smx[0] = smx[w]; sai[0] = sai[w];
            }
    }
    __syncthreads();
    const float MX = smx[0];
    const int   AI = sai[0];

    float4 e;
    e.x = expf(v.x - MX); e.y = expf(v.y - MX);
    e.z = expf(v.z - MX); e.w = expf(v.w - MX);
    float s = e.x + e.y + e.z + e.w;
#pragma unroll
    for (int off = 16; off > 0; off >>= 1) s += __shfl_down_sync(full, s, off);
    if (lane == 0) ssum[warp] = s;
    __syncthreads();
    if (t == 0) {
        float tot = 0.f;
        for (int w = 0; w < 8; ++w) tot += ssum[w];
        ssum[0] = tot;
    }
    __syncthreads();
    const float inv = 1.f / ssum[0];

    float4 o;
    o.x = (t*4+0 == AI) ? e.x*inv : -e.x*inv;
    o.y = (t*4+1 == AI) ? e.y*inv : -e.y*inv;
    o.z = (t*4+2 == AI) ? e.z*inv : -e.z*inv;
    o.w = (t*4+3 == AI) ? e.w*inv : -e.w*inv;
    reinterpret_cast<float4*>(&g_yn[(size_t)b * OUTD])[t] = o;
}

// ============================================================
// rate[o] = 1e-3 * |1 - ||W[o,:]||_2|^0.5
// ============================================================
__global__ __launch_bounds__(256) void rate_kernel(const float* __restrict__ W)
{
    const int o = blockIdx.x;
    const int t = threadIdx.x;
    const unsigned full = 0xffffffffu;
    float4 w = reinterpret_cast<const float4*>(&W[(size_t)o * IND])[t];
    float s = w.x*w.x + w.y*w.y + w.z*w.z + w.w*w.w;
#pragma unroll
    for (int off = 16; off > 0; off >>= 1) s += __shfl_down_sync(full, s, off);
    __shared__ float ssum[8];
    const int warp = t >> 5, lane = t & 31;
    if (lane == 0) ssum[warp] = s;
    __syncthreads();
    if (t == 0) {
        float tot = 0.f;
        for (int w2 = 0; w2 < 8; ++w2) tot += ssum[w2];
        float norm = sqrtf(tot);
        g_rate[o] = 1e-3f * sqrtf(fabsf(1.f - norm));
    }
}

// ============================================================
// m[o] = mean_b(yn[b,o] * u[b,o])
// ============================================================
__global__ __launch_bounds__(256) void col_partial_kernel()
{
    const int o = blockIdx.x * 256 + threadIdx.x;
    const int c = blockIdx.y;
    const int r0 = c * (BSZ / NCHUNK);
    float acc = 0.f;
#pragma unroll
    for (int r = 0; r < BSZ / NCHUNK; ++r) {
        const size_t off = (size_t)(r0 + r) * OUTD + o;
        acc += g_yn[off] * g_u[off];
    }
    g_P[c * OUTD + o] = acc;
}

__global__ __launch_bounds__(256) void m_final_kernel()
{
    const int o = blockIdx.x * 256 + threadIdx.x;
    float acc = 0.f;
    for (int c = 0; c < NCHUNK; ++c) acc += g_P[c * OUTD + o];
    g_m[o] = acc * (1.f / (float)BSZ);
}

// ============================================================
// out[o,i] = rate[o] * (sum_s S[s][o,i]/B - m[o]*W[o,i])
// ============================================================
__global__ __launch_bounds__(256) void epilogue_kernel(
    const float* __restrict__ W, float* __restrict__ out)
{
    const int o = blockIdx.x;
    const int t = threadIdx.x;
    const float m = g_m[o];
    const float r = g_rate[o];
    float4 wv = reinterpret_cast<const float4*>(&W[(size_t)o * IND])[t];
    float4 s = make_float4(0.f, 0.f, 0.f, 0.f);
#pragma unroll
    for (int sp = 0; sp < NSPLIT; ++sp) {
        float4 p = reinterpret_cast<const float4*>(
            &g_S[(size_t)sp * OUTD * IND + (size_t)o * IND])[t];
        s.x += p.x; s.y += p.y; s.z += p.z; s.w += p.w;
    }
    const float invB = 1.f / (float)BSZ;
    float4 ov;
    ov.x = r * (s.x * invB - m * wv.x);
    ov.y = r * (s.y * invB - m * wv.y);
    ov.z = r * (s.z * invB - m * wv.z);
    ov.w = r * (s.w * invB - m * wv.w);
    reinterpret_cast<float4*>(&out[(size_t)o * IND])[t] = ov;
}

// ============================================================
extern "C" void kernel_launch(void* const* d_in, const int* in_sizes, int n_in,
                              void* d_out, int out_size)
{
    const float* x = (const float*)d_in[0];   // [8192, 1024]
    const float* W = (const float*)d_in[1];   // [1024, 1024]
    const float* b = (const float*)d_in[2];   // [1024]
    float* out = (float*)d_out;               // [1024, 1024]

    cudaFuncSetAttribute(gemm_bf16v2_kernel,
                         cudaFuncAttributeMaxDynamicSharedMemorySize, SMEM_BYTES);

    float*    g_u_p;    cudaGetSymbolAddress((void**)&g_u_p,    g_u);
    float*    g_yn_p;   cudaGetSymbolAddress((void**)&g_yn_p,   g_yn);
    float*    g_S_p;    cudaGetSymbolAddress((void**)&g_S_p,    g_S);
    uint16_t* g_xh_p;   cudaGetSymbolAddress((void**)&g_xh_p,   g_xh);
    uint16_t* g_xl_p;   cudaGetSymbolAddress((void**)&g_xl_p,   g_xl);
    uint16_t* g_Wh_p;   cudaGetSymbolAddress((void**)&g_Wh_p,   g_Wh);
    uint16_t* g_Wl_p;   cudaGetSymbolAddress((void**)&g_Wl_p,   g_Wl);
    uint16_t* g_xTh_p;  cudaGetSymbolAddress((void**)&g_xTh_p,  g_xTh);
    uint16_t* g_xTl_p;  cudaGetSymbolAddress((void**)&g_xTl_p,  g_xTl);
    uint16_t* g_ynTh_p; cudaGetSymbolAddress((void**)&g_ynTh_p, g_ynTh);
    uint16_t* g_ynTl_p; cudaGetSymbolAddress((void**)&g_ynTl_p, g_ynTl);

    // split inputs to bf16 hi/lo (once)
    split_kernel<<<(BSZ*IND/4 + 255)/256, 256>>>(x, g_xh_p, g_xl_p, BSZ*IND/4);
    split_kernel<<<(OUTD*IND/4 + 255)/256, 256>>>(W, g_Wh_p, g_Wl_p, OUTD*IND/4);
    transpose_split_kernel<<<dim3(IND/32, BSZ/32), dim3(32, 8)>>>(
        x, g_xTh_p, g_xTl_p, BSZ, IND);

    // u = x @ W^T + b
    gemm_bf16v2_kernel<<<dim3(OUTD/128, BSZ/128, 1), 256, SMEM_BYTES>>>(
        g_xh_p, g_xl_p, IND, g_Wh_p, g_Wl_p, IND,
        0, g_u_p, OUTD, 0, b, IND / BK);
    // yn = negate_non_maximal(softmax(u))
    softmax_neg_kernel<<<BSZ, 256>>>();
    // yn^T split
    transpose_split_kernel<<<dim3(OUTD/32, BSZ/32), dim3(32, 8)>>>(
        g_yn_p, g_ynTh_p, g_ynTl_p, BSZ, OUTD);
    // per-row rate + m[o]
    rate_kernel<<<OUTD, 256>>>(W);
    col_partial_kernel<<<dim3(OUTD/256, NCHUNK), 256>>>();
    m_final_kernel<<<OUTD/256, 256>>>();
    // S[z] = yn^T @ x partials (split-K = 8)
    gemm_bf16v2_kernel<<<dim3(IND/128, OUTD/128, NSPLIT), 256, SMEM_BYTES>>>(
        g_ynTh_p, g_ynTl_p, BSZ, g_xTh_p, g_xTl_p, BSZ,
        BSZ/NSPLIT, g_S_p, IND, (size_t)OUTD * IND, nullptr,
        (BSZ/NSPLIT) / BK);
    // out = rate * (sum S / B - m*W)
    epilogue_kernel<<<OUTD, 256>>>(W, out);
}

// round 8
// speedup vs baseline: 2.2162x; 1.0378x over previous
#include <cuda_runtime.h>
#include <cstdint>
#include <math.h>

#define BSZ   8192
#define IND   1024
#define OUTD  1024
#define NSPLIT 8
#define NCHUNK 512

// ---- scratch (static device globals; no dynamic allocation) ----
__device__ float    g_u  [(size_t)BSZ * OUTD];           // 32 MB
__device__ float    g_yn [(size_t)BSZ * OUTD];           // 32 MB
__device__ float    g_P  [NCHUNK * OUTD];
__device__ float    g_m  [OUTD];
__device__ float    g_rate[OUTD];
__device__ float    g_S  [(size_t)NSPLIT * OUTD * IND];  // 32 MB
// pre-split bf16 operands
__device__ uint16_t g_xh [(size_t)BSZ * IND];
__device__ uint16_t g_xl [(size_t)BSZ * IND];
__device__ uint16_t g_Wh [(size_t)OUTD * IND];
__device__ uint16_t g_Wl [(size_t)OUTD * IND];
__device__ uint16_t g_xTh[(size_t)IND * BSZ];
__device__ uint16_t g_xTl[(size_t)IND * BSZ];
__device__ uint16_t g_ynTh[(size_t)OUTD * BSZ];
__device__ uint16_t g_ynTl[(size_t)OUTD * BSZ];

// ============================================================
// helpers
// ============================================================
__device__ __forceinline__ uint32_t bf16x2_rn(float hi, float lo) {
    uint32_t r;
    asm("cvt.rn.bf16x2.f32 %0, %1, %2;" : "=r"(r) : "f"(hi), "f"(lo));
    return r;
}
__device__ __forceinline__ void mma_bf16_k16(float c[4], const uint32_t a[4],
                                             const uint32_t b[2])
{
    asm volatile(
        "mma.sync.aligned.m16n8k16.row.col.f32.bf16.bf16.f32 "
        "{%0,%1,%2,%3}, {%4,%5,%6,%7}, {%8,%9}, {%0,%1,%2,%3};\n"
        : "+f"(c[0]), "+f"(c[1]), "+f"(c[2]), "+f"(c[3])
        : "r"(a[0]), "r"(a[1]), "r"(a[2]), "r"(a[3]),
          "r"(b[0]), "r"(b[1]));
}
__device__ __forceinline__ void ldsm_x4(uint32_t r[4], uint32_t addr) {
    asm volatile("ldmatrix.sync.aligned.m8n8.x4.shared.b16 {%0,%1,%2,%3}, [%4];"
        : "=r"(r[0]), "=r"(r[1]), "=r"(r[2]), "=r"(r[3]) : "r"(addr));
}
#define CP_ASYNC16(saddr, gptr) \
    asm volatile("cp.async.cg.shared.global [%0], [%1], 16;" \
        :: "r"(saddr), "l"(gptr))
#define CP_COMMIT()  asm volatile("cp.async.commit_group;")
#define CP_WAIT(n)   asm volatile("cp.async.wait_group %0;" :: "n"(n))

// Stage geometry: K=32 bf16, A = 256 rows, B = 128 rows, stride 40 bf16
#define BK      32
#define BM      256
#define BN      128
#define STRIDE  40
#define SM_AH   0
#define SM_AL   (BM * STRIDE * 2)                 // 20480
#define SM_BH   (2 * BM * STRIDE * 2)             // 40960
#define SM_BL   (2 * BM * STRIDE * 2 + BN * STRIDE * 2)   // 51200
#define STAGE_B (2 * BM * STRIDE * 2 + 2 * BN * STRIDE * 2) // 61440
#define SMEM_BYTES (2 * STAGE_B)                  // 122880

__device__ __forceinline__ void fill_stage(
    uint32_t sbase, int t,
    const uint16_t* __restrict__ Ah, const uint16_t* __restrict__ Al, int lda,
    const uint16_t* __restrict__ Bh, const uint16_t* __restrict__ Bl, int ldb,
    int m0, int n0, int ks0)
{
    // A: 256 rows x 4 16B-chunks = 1024 chunks per buffer
#pragma unroll
    for (int i = 0; i < 2; ++i) {
        const int c   = t + 512 * i;
        const int row = c >> 2;
        const int c16 = c & 3;
        const size_t go = (size_t)(m0 + row) * lda + ks0 + c16 * 8;
        const uint32_t so = (uint32_t)((row * STRIDE + c16 * 8) * 2);
        CP_ASYNC16(sbase + SM_AH + so, Ah + go);
        CP_ASYNC16(sbase + SM_AL + so, Al + go);
    }
    // B: 128 rows x 4 chunks = 512 chunks per buffer
    {
        const int row = t >> 2;
        const int c16 = t & 3;
        const size_t go = (size_t)(n0 + row) * ldb + ks0 + c16 * 8;
        const uint32_t so = (uint32_t)((row * STRIDE + c16 * 8) * 2);
        CP_ASYNC16(sbase + SM_BH + so, Bh + go);
        CP_ASYNC16(sbase + SM_BL + so, Bl + go);
    }
}

// ============================================================
// bf16x3 pipelined mma.sync GEMM.
// D[m0+r][n0+c] = sum_k A[m][k]*B[n][k] (+bias[n]); A,B pre-split bf16 K-major.
// CTA 256x128, 512 thr / 16 warps (4M x 4N), warp tile 64x32, K=32 stages,
// double buffer, ONE sync per stage.
// ============================================================
__global__ __launch_bounds__(512, 1) void gemm_bf16v3_kernel(
    const uint16_t* __restrict__ Ah, const uint16_t* __restrict__ Al, int lda,
    const uint16_t* __restrict__ Bh, const uint16_t* __restrict__ Bl, int ldb,
    int kzstep, float* __restrict__ dstBase, int ldd, size_t zstride,
    const float* __restrict__ bias, int nstages)
{
    extern __shared__ uint16_t sm[];
    const uint32_t sbase0 = (uint32_t)__cvta_generic_to_shared(sm);

    const int t     = threadIdx.x;
    const int lane  = t & 31;
    const int warp  = t >> 5;
    const int warpM = warp & 3;    // 0..3
    const int warpN = warp >> 2;   // 0..3
    const int m0    = blockIdx.y * BM;
    const int n0    = blockIdx.x * BN;
    const int kbase = blockIdx.z * kzstep;
    float* dst = dstBase + (size_t)blockIdx.z * zstride;

    const int gr   = lane >> 2;
    const int la15 = lane & 15;
    const int lhi  = lane >> 4;

    uint32_t aoff[4], boff[2];
#pragma unroll
    for (int mt = 0; mt < 4; ++mt)
        aoff[mt] = (uint32_t)(((warpM * 64 + mt * 16 + la15) * STRIDE
                               + lhi * 8) * 2);
#pragma unroll
    for (int p = 0; p < 2; ++p)
        boff[p] = (uint32_t)(((warpN * 32 + p * 16 + lhi * 8 + (lane & 7))
                               * STRIDE + ((lane >> 3) & 1) * 8) * 2);

    float c[4][4][4];
#pragma unroll
    for (int mt = 0; mt < 4; ++mt)
#pragma unroll
        for (int nt = 0; nt < 4; ++nt)
#pragma unroll
            for (int e = 0; e < 4; ++e) c[mt][nt][e] = 0.f;

    fill_stage(sbase0, t, Ah, Al, lda, Bh, Bl, ldb, m0, n0, kbase);
    CP_COMMIT();

    for (int s = 0; s < nstages; ++s) {
        CP_WAIT(0);          // fill(s) complete
        __syncthreads();     // all warps past consume(s-1), data visible
        if (s + 1 < nstages) {
            fill_stage(sbase0 + ((s + 1) & 1) * STAGE_B, t,
                       Ah, Al, lda, Bh, Bl, ldb, m0, n0,
                       kbase + (s + 1) * BK);
            CP_COMMIT();     // overlaps with consume(s) below
        }

        const uint32_t sb  = sbase0 + (s & 1) * STAGE_B;
        const uint32_t sAh = sb + SM_AH;
        const uint32_t sAl = sb + SM_AL;
        const uint32_t sBh = sb + SM_BH;
        const uint32_t sBl = sb + SM_BL;

#pragma unroll
        for (int ks = 0; ks < 2; ++ks) {
            const uint32_t ko = (uint32_t)(ks * 32);
            uint32_t ah[4][4], bb[4][2], t4[4];

#pragma unroll
            for (int mt = 0; mt < 4; ++mt)
                ldsm_x4(ah[mt], sAh + aoff[mt] + ko);
#pragma unroll
            for (int p = 0; p < 2; ++p) {
                ldsm_x4(t4, sBh + boff[p] + ko);
                bb[2*p][0] = t4[0]; bb[2*p][1] = t4[1];
                bb[2*p+1][0] = t4[2]; bb[2*p+1][1] = t4[3];
            }
            // hi * hi
#pragma unroll
            for (int mt = 0; mt < 4; ++mt)
#pragma unroll
                for (int nt = 0; nt < 4; ++nt)
                    mma_bf16_k16(c[mt][nt], ah[mt], bb[nt]);
            // hi * lo
            {
                uint32_t bl[4][2];
#pragma unroll
                for (int p = 0; p < 2; ++p) {
                    ldsm_x4(t4, sBl + boff[p] + ko);
                    bl[2*p][0] = t4[0]; bl[2*p][1] = t4[1];
                    bl[2*p+1][0] = t4[2]; bl[2*p+1][1] = t4[3];
                }
#pragma unroll
                for (int mt = 0; mt < 4; ++mt)
#pragma unroll
                    for (int nt = 0; nt < 4; ++nt)
                        mma_bf16_k16(c[mt][nt], ah[mt], bl[nt]);
            }
            // lo * hi
            {
                uint32_t al[4][4];
#pragma unroll
                for (int mt = 0; mt < 4; ++mt)
                    ldsm_x4(al[mt], sAl + aoff[mt] + ko);
#pragma unroll
                for (int mt = 0; mt < 4; ++mt)
#pragma unroll
                    for (int nt = 0; nt < 4; ++nt)
                        mma_bf16_k16(c[mt][nt], al[mt], bb[nt]);
            }
        }
    }

    // ---- epilogue ----
#pragma unroll
    for (int mt = 0; mt < 4; ++mt) {
        const int r = m0 + warpM * 64 + mt * 16 + gr;
#pragma unroll
        for (int nt = 0; nt < 4; ++nt) {
            const int cc = n0 + warpN * 32 + nt * 8 + (lane & 3) * 2;
            float2 v0 = make_float2(c[mt][nt][0], c[mt][nt][1]);
            float2 v1 = make_float2(c[mt][nt][2], c[mt][nt][3]);
            if (bias) {
                const float b0 = __ldg(&bias[cc]);
                const float b1 = __ldg(&bias[cc + 1]);
                v0.x += b0; v0.y += b1;
                v1.x += b0; v1.y += b1;
            }
            *reinterpret_cast<float2*>(&dst[(size_t)r * ldd + cc])       = v0;
            *reinterpret_cast<float2*>(&dst[(size_t)(r + 8) * ldd + cc]) = v1;
        }
    }
}

// ============================================================
// Elementwise split: v -> hi = trunc-bf16(v), lo = rn-bf16(v - hi)
// ============================================================
__global__ __launch_bounds__(256) void split_kernel(
    const float* __restrict__ src, uint16_t* __restrict__ dh,
    uint16_t* __restrict__ dl, int n4)
{
    const int i = blockIdx.x * 256 + threadIdx.x;
    if (i >= n4) return;
    float4 v = reinterpret_cast<const float4*>(src)[i];
    uint32_t x0 = __float_as_uint(v.x), x1 = __float_as_uint(v.y);
    uint32_t x2 = __float_as_uint(v.z), x3 = __float_as_uint(v.w);
    uint32_t h01 = __byte_perm(x0, x1, 0x7632);
    uint32_t h23 = __byte_perm(x2, x3, 0x7632);
    float l0 = v.x - __uint_as_float(x0 & 0xFFFF0000u);
    float l1 = v.y - __uint_as_float(x1 & 0xFFFF0000u);
    float l2 = v.z - __uint_as_float(x2 & 0xFFFF0000u);
    float l3 = v.w - __uint_as_float(x3 & 0xFFFF0000u);
    reinterpret_cast<uint2*>(dh)[i] = make_uint2(h01, h23);
    reinterpret_cast<uint2*>(dl)[i] =
        make_uint2(bf16x2_rn(l1, l0), bf16x2_rn(l3, l2));
}

// ============================================================
// Transpose + split: src fp32 [R][C] -> dsthi/dstlo bf16 [C][R]
// ============================================================
__global__ __launch_bounds__(256) void transpose_split_kernel(
    const float* __restrict__ src, uint16_t* __restrict__ dh,
    uint16_t* __restrict__ dl, int R, int C)
{
    __shared__ float tile[32][33];
    const int c0 = blockIdx.x * 32;
    const int r0 = blockIdx.y * 32;
    const int tx = threadIdx.x, ty = threadIdx.y;
#pragma unroll
    for (int i = 0; i < 4; ++i)
        tile[ty + i*8][tx] = src[(size_t)(r0 + ty + i*8) * C + c0 + tx];
    __syncthreads();
#pragma unroll
    for (int i = 0; i < 4; ++i) {
        float v = tile[tx][ty + i*8];
        uint32_t u = __float_as_uint(v);
        uint16_t hi = (uint16_t)(u >> 16);
        float lo = v - __uint_as_float(u & 0xFFFF0000u);
        uint32_t lop = bf16x2_rn(lo, lo);
        const size_t o = (size_t)(c0 + ty + i*8) * R + r0 + tx;
        dh[o] = hi;
        dl[o] = (uint16_t)(lop & 0xFFFF);
    }
}

// ============================================================
// Per-row softmax + negate-non-maximal
// ============================================================
__global__ __launch_bounds__(256) void softmax_neg_kernel()
{
    const int b = blockIdx.x;
    const int t = threadIdx.x;
    const unsigned full = 0xffffffffu;

    float4 v = reinterpret_cast<const float4*>(&g_u[(size_t)b * OUTD])[t];

    float mx = v.x; int ai = t*4;
    if (v.y > mx) { mx = v.y; ai = t*4+1; }
    if (v.z > mx) { mx = v.z; ai = t*4+2; }
    if (v.w > mx) { mx = v.w; ai = t*4+3; }

#pragma unroll
    for (int off = 16; off > 0; off >>= 1) {
        float omx = __shfl_down_sync(full, mx, off);
        int   oai = __shfl_down_sync(full, ai, off);
        if (omx > mx || (omx == mx && oai < ai)) { mx = omx; ai = oai; }
    }
    __shared__ float smx[8];
    __shared__ int   sai[8];
    __shared__ float ssum[8];
    const int warp = t >> 5, lane = t & 31;
    if (lane == 0) { smx[warp] = mx; sai[warp] = ai; }
    __syncthreads();
    if (t == 0) {
        for (int w = 1; w < 8; ++w)
            if (smx[w] > smx[0] || (smx[w] == smx[0] && sai[w] < sai[0])) {
                smx[0] = smx[w]; sai[0] = sai[w];
            }
    }
    __syncthreads();
    const float MX = smx[0];
    const int   AI = sai[0];

    float4 e;
    e.x = expf(v.x - MX); e.y = expf(v.y - MX);
    e.z = expf(v.z - MX); e.w = expf(v.w - MX);
    float s = e.x + e.y + e.z + e.w;
#pragma unroll
    for (int off = 16; off > 0; off >>= 1) s += __shfl_down_sync(full, s, off);
    if (lane == 0) ssum[warp] = s;
    __syncthreads();
    if (t == 0) {
        float tot = 0.f;
        for (int w = 0; w < 8; ++w) tot += ssum[w];
        ssum[0] = tot;
    }
    __syncthreads();
    const float inv = 1.f / ssum[0];

    float4 o;
    o.x = (t*4+0 == AI) ? e.x*inv : -e.x*inv;
    o.y = (t*4+1 == AI) ? e.y*inv : -e.y*inv;
    o.z = (t*4+2 == AI) ? e.z*inv : -e.z*inv;
    o.w = (t*4+3 == AI) ? e.w*inv : -e.w*inv;
    reinterpret_cast<float4*>(&g_yn[(size_t)b * OUTD])[t] = o;
}

// ============================================================
// rate[o] = 1e-3 * |1 - ||W[o,:]||_2|^0.5
// ============================================================
__global__ __launch_bounds__(256) void rate_kernel(const float* __restrict__ W)
{
    const int o = blockIdx.x;
    const int t = threadIdx.x;
    const unsigned full = 0xffffffffu;
    float4 w = reinterpret_cast<const float4*>(&W[(size_t)o * IND])[t];
    float s = w.x*w.x + w.y*w.y + w.z*w.z + w.w*w.w;
#pragma unroll
    for (int off = 16; off > 0; off >>= 1) s += __shfl_down_sync(full, s, off);
    __shared__ float ssum[8];
    const int warp = t >> 5, lane = t & 31;
    if (lane == 0) ssum[warp] = s;
    __syncthreads();
    if (t == 0) {
        float tot = 0.f;
        for (int w2 = 0; w2 < 8; ++w2) tot += ssum[w2];
        float norm = sqrtf(tot);
        g_rate[o] = 1e-3f * sqrtf(fabsf(1.f - norm));
    }
}

// ============================================================
// m[o] = mean_b(yn[b,o] * u[b,o])
// ============================================================
__global__ __launch_bounds__(256) void col_partial_kernel()
{
    const int o = blockIdx.x * 256 + threadIdx.x;
    const int c = blockIdx.y;
    const int r0 = c * (BSZ / NCHUNK);
    float acc = 0.f;
#pragma unroll
    for (int r = 0; r < BSZ / NCHUNK; ++r) {
        const size_t off = (size_t)(r0 + r) * OUTD + o;
        acc += g_yn[off] * g_u[off];
    }
    g_P[c * OUTD + o] = acc;
}

__global__ __launch_bounds__(256) void m_final_kernel()
{
    const int o = blockIdx.x * 256 + threadIdx.x;
    float acc = 0.f;
    for (int c = 0; c < NCHUNK; ++c) acc += g_P[c * OUTD + o];
    g_m[o] = acc * (1.f / (float)BSZ);
}

// ============================================================
// out[o,i] = rate[o] * (sum_s S[s][o,i]/B - m[o]*W[o,i])
// ============================================================
__global__ __launch_bounds__(256) void epilogue_kernel(
    const float* __restrict__ W, float* __restrict__ out)
{
    const int o = blockIdx.x;
    const int t = threadIdx.x;
    const float m = g_m[o];
    const float r = g_rate[o];
    float4 wv = reinterpret_cast<const float4*>(&W[(size_t)o * IND])[t];
    float4 s = make_float4(0.f, 0.f, 0.f, 0.f);
#pragma unroll
    for (int sp = 0; sp < NSPLIT; ++sp) {
        float4 p = reinterpret_cast<const float4*>(
            &g_S[(size_t)sp * OUTD * IND + (size_t)o * IND])[t];
        s.x += p.x; s.y += p.y; s.z += p.z; s.w += p.w;
    }
    const float invB = 1.f / (float)BSZ;
    float4 ov;
    ov.x = r * (s.x * invB - m * wv.x);
    ov.y = r * (s.y * invB - m * wv.y);
    ov.z = r * (s.z * invB - m * wv.z);
    ov.w = r * (s.w * invB - m * wv.w);
    reinterpret_cast<float4*>(&out[(size_t)o * IND])[t] = ov;
}

// ============================================================
extern "C" void kernel_launch(void* const* d_in, const int* in_sizes, int n_in,
                              void* d_out, int out_size)
{
    const float* x = (const float*)d_in[0];   // [8192, 1024]
    const float* W = (const float*)d_in[1];   // [1024, 1024]
    const float* b = (const float*)d_in[2];   // [1024]
    float* out = (float*)d_out;               // [1024, 1024]

    cudaFuncSetAttribute(gemm_bf16v3_kernel,
                         cudaFuncAttributeMaxDynamicSharedMemorySize, SMEM_BYTES);

    float*    g_u_p;    cudaGetSymbolAddress((void**)&g_u_p,    g_u);
    float*    g_yn_p;   cudaGetSymbolAddress((void**)&g_yn_p,   g_yn);
    float*    g_S_p;    cudaGetSymbolAddress((void**)&g_S_p,    g_S);
    uint16_t* g_xh_p;   cudaGetSymbolAddress((void**)&g_xh_p,   g_xh);
    uint16_t* g_xl_p;   cudaGetSymbolAddress((void**)&g_xl_p,   g_xl);
    uint16_t* g_Wh_p;   cudaGetSymbolAddress((void**)&g_Wh_p,   g_Wh);
    uint16_t* g_Wl_p;   cudaGetSymbolAddress((void**)&g_Wl_p,   g_Wl);
    uint16_t* g_xTh_p;  cudaGetSymbolAddress((void**)&g_xTh_p,  g_xTh);
    uint16_t* g_xTl_p;  cudaGetSymbolAddress((void**)&g_xTl_p,  g_xTl);
    uint16_t* g_ynTh_p; cudaGetSymbolAddress((void**)&g_ynTh_p, g_ynTh);
    uint16_t* g_ynTl_p; cudaGetSymbolAddress((void**)&g_ynTl_p, g_ynTl);

    // split inputs to bf16 hi/lo (once)
    split_kernel<<<(BSZ*IND/4 + 255)/256, 256>>>(x, g_xh_p, g_xl_p, BSZ*IND/4);
    split_kernel<<<(OUTD*IND/4 + 255)/256, 256>>>(W, g_Wh_p, g_Wl_p, OUTD*IND/4);
    transpose_split_kernel<<<dim3(IND/32, BSZ/32), dim3(32, 8)>>>(
        x, g_xTh_p, g_xTl_p, BSZ, IND);

    // u = x @ W^T + b
    gemm_bf16v3_kernel<<<dim3(OUTD/BN, BSZ/BM, 1), 512, SMEM_BYTES>>>(
        g_xh_p, g_xl_p, IND, g_Wh_p, g_Wl_p, IND,
        0, g_u_p, OUTD, 0, b, IND / BK);
    // yn = negate_non_maximal(softmax(u))
    softmax_neg_kernel<<<BSZ, 256>>>();
    // yn^T split
    transpose_split_kernel<<<dim3(OUTD/32, BSZ/32), dim3(32, 8)>>>(
        g_yn_p, g_ynTh_p, g_ynTl_p, BSZ, OUTD);
    // per-row rate + m[o]
    rate_kernel<<<OUTD, 256>>>(W);
    col_partial_kernel<<<dim3(OUTD/256, NCHUNK), 256>>>();
    m_final_kernel<<<OUTD/256, 256>>>();
    // S[z] = yn^T @ x partials (split-K = 8)
    gemm_bf16v3_kernel<<<dim3(IND/BN, OUTD/BM, NSPLIT), 512, SMEM_BYTES>>>(
        g_ynTh_p, g_ynTl_p, BSZ, g_xTh_p, g_xTl_p, BSZ,
        BSZ/NSPLIT, g_S_p, IND, (size_t)OUTD * IND, nullptr,
        (BSZ/NSPLIT) / BK);
    // out = rate * (sum S / B - m*W)
    epilogue_kernel<<<OUTD, 256>>>(W, out);
}